// round 13
// baseline (speedup 1.0000x reference)
#include <cuda_runtime.h>
#include <math.h>

// ---------------------------------------------------------------------------
// expression[c,g] = bias1[gene_ix[g]] + sum_{frags in bucket c*gene_n+g}
//                   dot(sin(coords[f,:,None]*freq+shift).reshape(40), w)
// Per-fragment scalar g0(x)+g1(y). R13 = R12 (nearest-node LUT, TAB=1024,
// magic-round, R5 scan/RED) + software-pipelined loads: next window's
// coords/ix LDGs issued before current window's compute, hiding the
// long-scoreboard stall behind compute+scan. 6 blocks/SM, one full wave.
// ---------------------------------------------------------------------------

#define TAB    1024
#define TPTS   (TAB + 1)          // nodes 0..TAB inclusive
#define TPAD   2048               // padded table length (mask range)
#define T_LO   (-8.0f)
#define T_HI   ( 8.0f)
#define FULL   0xffffffffu
#define MAGIC  8388608.0f         // 2^23
#define NBLK   888                // 6 blocks/SM x 148 SMs = one wave

__device__ float g_tbl[2 * TPTS]; // value-only tables (x then y)

// ---------------------------------------------------------------------------
// prep: first TBL_BLOCKS blocks build the LUT (warp per node, lane per freq
// term); remaining blocks vector-init out = bias[gene_ix[col]].
// ---------------------------------------------------------------------------
#define TBL_POINTS  (2 * TPTS)
#define TBL_BLOCKS  ((TBL_POINTS * 32 + 255) / 256)
#define INIT_ROWS   8

__global__ void prep_kernel(const float* __restrict__ freqs,
                            const float* __restrict__ shifts,
                            const float* __restrict__ w,
                            const float* __restrict__ bias,
                            const int*   __restrict__ gene_ix,
                            float*       __restrict__ out,
                            int gene_n, int total)
{
    if (blockIdx.x < TBL_BLOCKS) {
        int gw   = blockIdx.x * (blockDim.x >> 5) + (threadIdx.x >> 5);
        int lane = threadIdx.x & 31;
        if (gw < TBL_POINTS) {
            int which = gw / TPTS;
            int k     = gw % TPTS;
            float x   = T_LO + (float)k * ((T_HI - T_LO) / (float)TAB);
            float v   = 0.f;
            if (lane < 20)
                v = w[which * 20 + lane] * sinf(fmaf(x, freqs[lane], shifts[lane]));
            #pragma unroll
            for (int off = 16; off; off >>= 1)
                v += __shfl_down_sync(FULL, v, off);
            if (lane == 0) g_tbl[which * TPTS + k] = v;
        }
        return;
    }

    int ib = blockIdx.x - TBL_BLOCKS;

    if ((gene_n & 3) == 0 && gene_n <= 4096 && total % gene_n == 0) {
        __shared__ float pb[4096];
        for (int g = threadIdx.x; g < gene_n; g += blockDim.x)
            pb[g] = __ldg(&bias[__ldg(&gene_ix[g])]);
        __syncthreads();

        const float4* pb4 = reinterpret_cast<const float4*>(pb);
        float4*       o4  = reinterpret_cast<float4*>(out);
        int row_q  = gene_n >> 2;
        int rows   = total / gene_n;
        int r0     = ib * INIT_ROWS;
        int nq     = min(INIT_ROWS, rows - r0) * row_q;
        if (nq <= 0) return;
        long base4 = (long)r0 * row_q;
        for (int t = threadIdx.x; t < nq; t += blockDim.x)
            o4[base4 + t] = pb4[t % row_q];
    } else {
        for (long i = (long)ib * blockDim.x * INIT_ROWS * 4 + threadIdx.x;
             i < (long)total && i < (long)(ib + 1) * blockDim.x * INIT_ROWS * 4;
             i += blockDim.x)
            out[i] = __ldg(&bias[__ldg(&gene_ix[(int)(i % gene_n)])]);
    }
}

// ---------------------------------------------------------------------------
// Nearest-node lookup: k = round((x - T_LO) * scale) via magic-float add.
// Mask keeps any index inside the padded table (memory-safe).
__device__ __forceinline__ float nn1(const float* __restrict__ s, float x)
{
    const float scale = (float)TAB / (T_HI - T_LO);
    const float offs  = -T_LO * scale;
    float u = fmaf(x, scale, offs);          // in (0, TAB) for |x|<8
    float m = u + MAGIC;                     // RN -> mantissa = round(u)
    int   k = __float_as_int(m) & (TPAD - 1);
    return s[k];
}

__global__ void __launch_bounds__(256, 6)
frag_kernel(const float4* __restrict__ coords2,   // 2 frags per element
            const int4*   __restrict__ ix4,       // 4 bucket ids per element
            const float*  __restrict__ coords_raw,
            const int*    __restrict__ ix_raw,
            float*        __restrict__ out,
            int nquads, int F)
{
    __shared__ float s0[TPAD];    // 8 KB
    __shared__ float s1[TPAD];    // 8 KB
    for (int i = threadIdx.x; i < 2 * TPTS; i += blockDim.x) {
        float v = g_tbl[i];
        if (i < TPTS) s0[i] = v; else s1[i - TPTS] = v;
    }
    __syncthreads();

    // Leftover fragments (F % 4): one thread.
    if (blockIdx.x == 0 && threadIdx.x == 0) {
        for (int f = 4 * nquads; f < F; ++f) {
            float x = coords_raw[2 * f], y = coords_raw[2 * f + 1];
            atomicAdd(out + ix_raw[f], nn1(s0, x) + nn1(s1, y));
        }
    }

    int  lane   = threadIdx.x & 31;
    int  gwarp  = (blockIdx.x * blockDim.x + threadIdx.x) >> 5;
    int  nwarps = (NBLK * 256) >> 5;
    long stride = (long)nwarps * 32;

    // ---- software pipeline: preload window 0 ----
    long q = (long)gwarp * 32 + lane;
    bool valid = q < (long)nquads;
    float4 cA = make_float4(0,0,0,0), cB = make_float4(0,0,0,0);
    int4   bb = make_int4(-1,-1,-1,-1);
    if (valid) {
        cA = __ldcs(&coords2[2 * q]);
        cB = __ldcs(&coords2[2 * q + 1]);
        bb = __ldcs(&ix4[q]);
    }

    for (long qbase = (long)gwarp * 32; qbase < (long)nquads; qbase += stride) {
        // ---- issue next window's loads first (overlap with compute) ----
        long qn = qbase + stride + lane;
        bool vn = qn < (long)nquads;
        float4 nA = make_float4(0,0,0,0), nB = make_float4(0,0,0,0);
        int4   nb = make_int4(-1,-1,-1,-1);
        if (vn) {
            nA = __ldcs(&coords2[2 * qn]);
            nB = __ldcs(&coords2[2 * qn + 1]);
            nb = __ldcs(&ix4[qn]);
        }

        // ---- compute current window ----
        float v0 = nn1(s0, cA.x) + nn1(s1, cA.y);
        float v1 = nn1(s0, cA.z) + nn1(s1, cA.w);
        float v2 = nn1(s0, cB.x) + nn1(s1, cB.y);
        float v3 = nn1(s0, cB.z) + nn1(s1, cB.w);

        bool e01 = (bb.x == bb.y), e12 = (bb.y == bb.z), e23 = (bb.z == bb.w);
        float c0 = v0;
        float c1 = v1 + (e01 ? c0 : 0.f);
        float c2 = v2 + (e12 ? c1 : 0.f);
        float c3 = v3 + (e23 ? c2 : 0.f);
        bool  same = e01 && e12 && e23;
        float hsum = !e01 ? c0 : (!e12 ? c1 : c2);

        int  st_prev = __shfl_up_sync(FULL, bb.w, 1);
        bool cont    = (lane > 0) && same && (st_prev == bb.w);

        unsigned hb    = __ballot_sync(FULL, !cont);
        unsigned below = hb & (0xffffffffu >> (31 - lane));
        int seg = 31 - __clz(below);                 // bit 0 always set

        float S = c3;
        #pragma unroll
        for (int off = 1; off < 32; off <<= 1) {
            float n = __shfl_up_sync(FULL, S, off);
            if (lane - off >= seg) S += n;
        }

        float Sprev = __shfl_up_sync(FULL, S, 1);
        int   nb0   = __shfl_down_sync(FULL, bb.x, 1);
        bool consumed = (lane < 31) && (nb0 == bb.w);

        bool f_int1 = valid && !e12 && !e01;
        bool f_int2 = valid && !e23 && !(e01 && e12);
        bool f_head = valid && !same;
        bool f_tail = valid && !consumed;
        float hv = hsum + ((lane > 0 && st_prev == bb.x) ? Sprev : 0.f);

        if (f_int1) atomicAdd(out + bb.y, c1);
        if (f_int2) atomicAdd(out + bb.z, c2);
        if (f_head) atomicAdd(out + bb.x, hv);
        if (f_tail) atomicAdd(out + bb.w, S);

        // ---- rotate pipeline ----
        cA = nA; cB = nB; bb = nb; valid = vn;
    }
}

// ---------------------------------------------------------------------------
extern "C" void kernel_launch(void* const* d_in, const int* in_sizes, int n_in,
                              void* d_out, int out_size)
{
    // 0 coords, 1 cellxgene_ix, 2 cell_n, 3 gene_n, 4 gene_ix,
    // 5 frequencies, 6 shifts, 7 weight1, 8 bias1
    int off = (n_in >= 9) ? 0 : -2;

    const float* coords  = (const float*)d_in[0];
    const int*   ix      = (const int*)  d_in[1];
    const int*   gene_ix = (const int*)  d_in[4 + off];
    const float* freqs   = (const float*)d_in[5 + off];
    const float* shifts  = (const float*)d_in[6 + off];
    const float* w       = (const float*)d_in[7 + off];
    const float* bias    = (const float*)d_in[8 + off];

    int F      = in_sizes[0] / 2;
    int gene_n = in_sizes[4 + off];
    float* out = (float*)d_out;

    int init_blocks;
    if ((gene_n & 3) == 0 && gene_n <= 4096 && out_size % gene_n == 0) {
        int rows = out_size / gene_n;
        init_blocks = (rows + INIT_ROWS - 1) / INIT_ROWS;
    } else {
        init_blocks = (out_size + 256 * INIT_ROWS * 4 - 1) / (256 * INIT_ROWS * 4);
    }
    prep_kernel<<<TBL_BLOCKS + init_blocks, 256>>>(freqs, shifts, w, bias,
                                                   gene_ix, out, gene_n, out_size);

    int nquads = F / 4;
    frag_kernel<<<NBLK, 256>>>((const float4*)coords, (const int4*)ix,
                               coords, ix, out, nquads, F);
}

// round 14
// speedup vs baseline: 1.0389x; 1.0389x over previous
#include <cuda_runtime.h>
#include <math.h>

// ---------------------------------------------------------------------------
// expression[c,g] = bias1[gene_ix[g]] + sum_{frags in bucket c*gene_n+g}
//                   dot(sin(coords[f,:,None]*freq+shift).reshape(40), w)
// Per-fragment scalar g0(x)+g1(y) via nearest-node LUT (TAB=1024, magic-round).
// R14: NO cross-lane scan. Each lane handles 4 sorted fragments, combines
// in-register runs branchlessly, and fires 1-4 predicated global REDs
// (per-lane run totals). Zero shuffles/ballots in the hot loop.
// ---------------------------------------------------------------------------

#define TAB    1024
#define TPTS   (TAB + 1)          // nodes 0..TAB inclusive
#define TPAD   2048               // padded table length (mask range)
#define T_LO   (-8.0f)
#define T_HI   ( 8.0f)
#define FULL   0xffffffffu
#define MAGIC  8388608.0f         // 2^23

__device__ float g_tbl[2 * TPTS]; // value-only tables (x then y)

// ---------------------------------------------------------------------------
// prep: first TBL_BLOCKS blocks build the LUT (warp per node, lane per freq
// term); remaining blocks vector-init out = bias[gene_ix[col]].
// ---------------------------------------------------------------------------
#define TBL_POINTS  (2 * TPTS)
#define TBL_BLOCKS  ((TBL_POINTS * 32 + 255) / 256)
#define INIT_ROWS   8

__global__ void prep_kernel(const float* __restrict__ freqs,
                            const float* __restrict__ shifts,
                            const float* __restrict__ w,
                            const float* __restrict__ bias,
                            const int*   __restrict__ gene_ix,
                            float*       __restrict__ out,
                            int gene_n, int total)
{
    if (blockIdx.x < TBL_BLOCKS) {
        int gw   = blockIdx.x * (blockDim.x >> 5) + (threadIdx.x >> 5);
        int lane = threadIdx.x & 31;
        if (gw < TBL_POINTS) {
            int which = gw / TPTS;
            int k     = gw % TPTS;
            float x   = T_LO + (float)k * ((T_HI - T_LO) / (float)TAB);
            float v   = 0.f;
            if (lane < 20)
                v = w[which * 20 + lane] * sinf(fmaf(x, freqs[lane], shifts[lane]));
            #pragma unroll
            for (int off = 16; off; off >>= 1)
                v += __shfl_down_sync(FULL, v, off);
            if (lane == 0) g_tbl[which * TPTS + k] = v;
        }
        return;
    }

    int ib = blockIdx.x - TBL_BLOCKS;

    if ((gene_n & 3) == 0 && gene_n <= 4096 && total % gene_n == 0) {
        __shared__ float pb[4096];
        for (int g = threadIdx.x; g < gene_n; g += blockDim.x)
            pb[g] = __ldg(&bias[__ldg(&gene_ix[g])]);
        __syncthreads();

        const float4* pb4 = reinterpret_cast<const float4*>(pb);
        float4*       o4  = reinterpret_cast<float4*>(out);
        int row_q  = gene_n >> 2;
        int rows   = total / gene_n;
        int r0     = ib * INIT_ROWS;
        int nq     = min(INIT_ROWS, rows - r0) * row_q;
        if (nq <= 0) return;
        long base4 = (long)r0 * row_q;
        for (int t = threadIdx.x; t < nq; t += blockDim.x)
            o4[base4 + t] = pb4[t % row_q];
    } else {
        for (long i = (long)ib * blockDim.x * INIT_ROWS * 4 + threadIdx.x;
             i < (long)total && i < (long)(ib + 1) * blockDim.x * INIT_ROWS * 4;
             i += blockDim.x)
            out[i] = __ldg(&bias[__ldg(&gene_ix[(int)(i % gene_n)])]);
    }
}

// ---------------------------------------------------------------------------
// Nearest-node lookup: k = round((x - T_LO) * scale) via magic-float add.
// Mask keeps any index inside the padded table (memory-safe).
__device__ __forceinline__ float nn1(const float* __restrict__ s, float x)
{
    const float scale = (float)TAB / (T_HI - T_LO);
    const float offs  = -T_LO * scale;
    float u = fmaf(x, scale, offs);          // in (0, TAB) for |x|<8
    float m = u + MAGIC;                     // RN -> mantissa = round(u)
    int   k = __float_as_int(m) & (TPAD - 1);
    return s[k];
}

__global__ void __launch_bounds__(256)
frag_kernel(const float4* __restrict__ coords2,   // 2 frags per element
            const int4*   __restrict__ ix4,       // 4 bucket ids per element
            const float*  __restrict__ coords_raw,
            const int*    __restrict__ ix_raw,
            float*        __restrict__ out,
            int nquads, int F)
{
    __shared__ float s0[TPAD];    // 8 KB
    __shared__ float s1[TPAD];    // 8 KB -> 16 KB total, 8 blocks/SM
    for (int i = threadIdx.x; i < 2 * TPTS; i += blockDim.x) {
        float v = g_tbl[i];
        if (i < TPTS) s0[i] = v; else s1[i - TPTS] = v;
    }
    __syncthreads();

    // Leftover fragments (F % 4): one thread.
    if (blockIdx.x == 0 && threadIdx.x == 0) {
        for (int f = 4 * nquads; f < F; ++f) {
            float x = coords_raw[2 * f], y = coords_raw[2 * f + 1];
            atomicAdd(out + ix_raw[f], nn1(s0, x) + nn1(s1, y));
        }
    }

    int gtid    = blockIdx.x * blockDim.x + threadIdx.x;
    int nthr    = gridDim.x * blockDim.x;

    for (long q = gtid; q < (long)nquads; q += nthr) {
        float4 cA = __ldcs(&coords2[2 * q]);
        float4 cB = __ldcs(&coords2[2 * q + 1]);
        int4   bb = __ldcs(&ix4[q]);

        float v0 = nn1(s0, cA.x) + nn1(s1, cA.y);
        float v1 = nn1(s0, cA.z) + nn1(s1, cA.w);
        float v2 = nn1(s0, cB.x) + nn1(s1, cB.y);
        float v3 = nn1(s0, cB.z) + nn1(s1, cB.w);

        // Branchless cumulative run sums over the 4 sorted buckets.
        bool e01 = (bb.x == bb.y), e12 = (bb.y == bb.z), e23 = (bb.z == bb.w);
        float c0 = v0;
        float c1 = v1 + (e01 ? c0 : 0.f);
        float c2 = v2 + (e12 ? c1 : 0.f);
        float c3 = v3 + (e23 ? c2 : 0.f);
        bool  same = e01 && e12 && e23;
        float hsum = !e01 ? c0 : (!e12 ? c1 : c2);   // prefix run (if any boundary)

        // Per-lane run flushes: every fragment counted exactly once.
        bool f_head = !same;                  // run starting at x, ends inside
        bool f_int1 = !e01 && !e12;           // run {y}
        bool f_int2 = !e23 && !(e01 && e12);  // run ending at z, started after x
        //  tail run (ends at w) always flushes c3.

        if (f_head) atomicAdd(out + bb.x, hsum);
        if (f_int1) atomicAdd(out + bb.y, c1);
        if (f_int2) atomicAdd(out + bb.z, c2);
        atomicAdd(out + bb.w, c3);
    }
}

// ---------------------------------------------------------------------------
extern "C" void kernel_launch(void* const* d_in, const int* in_sizes, int n_in,
                              void* d_out, int out_size)
{
    // 0 coords, 1 cellxgene_ix, 2 cell_n, 3 gene_n, 4 gene_ix,
    // 5 frequencies, 6 shifts, 7 weight1, 8 bias1
    int off = (n_in >= 9) ? 0 : -2;

    const float* coords  = (const float*)d_in[0];
    const int*   ix      = (const int*)  d_in[1];
    const int*   gene_ix = (const int*)  d_in[4 + off];
    const float* freqs   = (const float*)d_in[5 + off];
    const float* shifts  = (const float*)d_in[6 + off];
    const float* w       = (const float*)d_in[7 + off];
    const float* bias    = (const float*)d_in[8 + off];

    int F      = in_sizes[0] / 2;
    int gene_n = in_sizes[4 + off];
    float* out = (float*)d_out;

    int init_blocks;
    if ((gene_n & 3) == 0 && gene_n <= 4096 && out_size % gene_n == 0) {
        int rows = out_size / gene_n;
        init_blocks = (rows + INIT_ROWS - 1) / INIT_ROWS;
    } else {
        init_blocks = (out_size + 256 * INIT_ROWS * 4 - 1) / (256 * INIT_ROWS * 4);
    }
    prep_kernel<<<TBL_BLOCKS + init_blocks, 256>>>(freqs, shifts, w, bias,
                                                   gene_ix, out, gene_n, out_size);

    int nquads = F / 4;
    frag_kernel<<<1184, 256>>>((const float4*)coords, (const int4*)ix,
                               coords, ix, out, nquads, F);
}